// round 1
// baseline (speedup 1.0000x reference)
#include <cuda_runtime.h>
#include <math.h>

#define NB 8
#define CIN 512
#define COUT 512
#define SDIM 512
#define HH 32
#define HY 65
#define HO 64

// ---------------- device scratch (static: no dynamic allocation allowed) ----
__device__ float g_s[NB * CIN];                  // style modulation s[b,i]
__device__ float g_demod[NB * COUT];             // demod[b,o]
__device__ float g_xs[NB * CIN * HH * HH];       // x * s * conv_scale
__device__ float g_wc[4 * CIN * 4 * COUT];       // per-class taps, [cls][i][tap(4)][o]
__device__ float g_y[NB * COUT * HY * HY];       // pre-blur transposed-conv output

// ---------------- k1: s[b,i] = style[b,:] . mod_w[i,:] * lin_scale + mod_b[i]
__global__ void k_style(const float* __restrict__ style,
                        const float* __restrict__ mod_w,
                        const float* __restrict__ mod_b) {
    int warp = (blockIdx.x * blockDim.x + threadIdx.x) >> 5;
    int lane = threadIdx.x & 31;
    if (warp >= NB * CIN) return;
    int b = warp >> 9;
    int i = warp & 511;
    const float* st = style + b * SDIM;
    const float* mw = mod_w + i * SDIM;
    float acc = 0.f;
    for (int d = lane; d < SDIM; d += 32) acc += st[d] * mw[d];
    #pragma unroll
    for (int off = 16; off; off >>= 1) acc += __shfl_down_sync(0xffffffffu, acc, off);
    if (lane == 0) {
        const float lin_scale = 0.04419417382415922f;  // 1/sqrt(512)
        g_s[warp] = acc * lin_scale + mod_b[i];
    }
}

// ---------------- k2: demod[b,o] = rsqrt(cs^2 * sum_i (sum_kk w^2) * s^2 + eps)
__global__ void k_demod(const float* __restrict__ weight) {
    int warp = (blockIdx.x * blockDim.x + threadIdx.x) >> 5;
    int lane = threadIdx.x & 31;
    if (warp >= NB * COUT) return;
    int b = warp >> 9;
    int o = warp & 511;
    float acc = 0.f;
    for (int i = lane; i < CIN; i += 32) {
        const float* wp = weight + (o * CIN + i) * 9;
        float ws = 0.f;
        #pragma unroll
        for (int k = 0; k < 9; k++) ws += wp[k] * wp[k];
        float sv = g_s[b * CIN + i];
        acc += ws * sv * sv;
    }
    #pragma unroll
    for (int off = 16; off; off >>= 1) acc += __shfl_down_sync(0xffffffffu, acc, off);
    if (lane == 0) {
        const float cs2 = 1.0f / 4608.0f;  // conv_scale^2, conv_scale = 1/sqrt(512*9)
        g_demod[warp] = rsqrtf(acc * cs2 + 1e-8f);
    }
}

// ---------------- k3: xs = x * s[b,i] * conv_scale
__global__ void k_xs(const float* __restrict__ x) {
    int idx = blockIdx.x * blockDim.x + threadIdx.x;
    if (idx < NB * CIN * HH * HH) {
        int bi = idx >> 10;  // (b*CIN + i), since HH*HH = 1024
        g_xs[idx] = x[idx] * g_s[bi] * 0.014731391274719739f;  // 1/sqrt(4608)
    }
}

// ---------------- k4: reorder weights into 4 parity-class tap tensors --------
// Transposed conv stride 2, flipped 3x3 kernel, pad k-1:
//   even out idx uses x[p'-1] (w[2]) and x[p'] (w[0]); odd out idx uses x[p'] (w[1]).
// class = (rows_odd?2:0)+(cols_odd?1:0); tap index t = dr*TC + dc.
__global__ void k_wc(const float* __restrict__ weight) {
    int idx = blockIdx.x * blockDim.x + threadIdx.x;
    if (idx >= COUT * CIN) return;
    int o = idx >> 9;
    int i = idx & 511;
    const float* wp = weight + idx * 9;  // (o*CIN + i)*9
    float w00 = wp[0], w01 = wp[1], w02 = wp[2];
    float w10 = wp[3], w11 = wp[4], w12 = wp[5];
    float w20 = wp[6], w21 = wp[7], w22 = wp[8];
    // cls0 (even,even): taps (dr,dc) -> w[2-2dr][2-2dc]
    float* p0 = g_wc + ((0 * CIN + i) * 4) * COUT + o;
    p0[0 * COUT] = w22; p0[1 * COUT] = w20; p0[2 * COUT] = w02; p0[3 * COUT] = w00;
    // cls1 (even rows, odd cols): t=dr -> w[2-2dr][1]
    float* p1 = g_wc + ((1 * CIN + i) * 4) * COUT + o;
    p1[0 * COUT] = w21; p1[1 * COUT] = w01; p1[2 * COUT] = 0.f; p1[3 * COUT] = 0.f;
    // cls2 (odd rows, even cols): t=dc -> w[1][2-2dc]
    float* p2 = g_wc + ((2 * CIN + i) * 4) * COUT + o;
    p2[0 * COUT] = w12; p2[1 * COUT] = w10; p2[2 * COUT] = 0.f; p2[3 * COUT] = 0.f;
    // cls3 (odd,odd): w[1][1]
    float* p3 = g_wc + ((3 * CIN + i) * 4) * COUT + o;
    p3[0 * COUT] = w11; p3[1 * COUT] = 0.f; p3[2 * COUT] = 0.f; p3[3 * COUT] = 0.f;
}

// ---------------- k5: per-class transposed-conv as tiled direct conv --------
// Block: 8x8 pixel tile (p',q' space) x 64 couts, 256 threads, thread = 4 pix x 4 cout.
template <int TR, int TC>
__global__ void k_conv() {
    constexpr int PH = (TR == 2) ? 33 : 32;
    constexpr int PW = (TC == 2) ? 33 : 32;
    constexpr int XR = 8 + TR - 1;
    constexpr int XC = 8 + TC - 1;
    constexpr int CI = 16;
    constexpr int CLS = ((TR == 1) ? 2 : 0) + ((TC == 1) ? 1 : 0);
    constexpr int PRY = (TR == 2) ? 0 : 1;  // output row parity
    constexpr int PCY = (TC == 2) ? 0 : 1;  // output col parity
    constexpr int TILES_C = (PW + 7) / 8;

    __shared__ float xsm[CI][XR][XC];
    __shared__ float wsm[CI][4][64];

    int tid = threadIdx.x;
    int b = blockIdx.z;
    int o0 = blockIdx.y * 64;
    int tile = blockIdx.x;
    int p0 = (tile / TILES_C) * 8;
    int q0 = (tile % TILES_C) * 8;
    int row0 = p0 - (TR - 1);
    int col0 = q0 - (TC - 1);

    int my = tid >> 4;           // 16 pixel groups
    int nx = tid & 15;           // 16 cout groups (x4)
    int tr_ = my >> 1;           // pixel row in tile [0,8)
    int qj0 = (my & 1) * 4;      // pixel col start in tile {0,4}

    float acc[4][4];
    #pragma unroll
    for (int j = 0; j < 4; j++)
        #pragma unroll
        for (int n = 0; n < 4; n++) acc[j][n] = 0.f;

    const float* xsb = g_xs + b * (CIN * HH * HH);

    for (int ic = 0; ic < CIN; ic += CI) {
        // stage input tile (with zero halo)
        for (int idx = tid; idx < CI * XR * XC; idx += 256) {
            int ii = idx / (XR * XC);
            int rem = idx - ii * (XR * XC);
            int r = rem / XC;
            int cc = rem - r * XC;
            int gr = row0 + r, gc = col0 + cc;
            float v = 0.f;
            if (gr >= 0 && gr < HH && gc >= 0 && gc < HH)
                v = xsb[(ic + ii) * (HH * HH) + gr * HH + gc];
            xsm[ii][r][cc] = v;
        }
        // stage weights [i][tap][o]
        for (int idx = tid; idx < CI * 4 * 64; idx += 256) {
            int ii = idx >> 8;
            int rem = idx & 255;
            int t = rem >> 6;
            int o = rem & 63;
            wsm[ii][t][o] = g_wc[((CLS * CIN + ic + ii) * 4 + t) * COUT + o0 + o];
        }
        __syncthreads();

        #pragma unroll 4
        for (int ii = 0; ii < CI; ii++) {
            #pragma unroll
            for (int dr = 0; dr < TR; dr++) {
                float xr[4 + TC - 1];
                #pragma unroll
                for (int j = 0; j < 4 + TC - 1; j++)
                    xr[j] = xsm[ii][tr_ + dr][qj0 + j];
                #pragma unroll
                for (int dc = 0; dc < TC; dc++) {
                    const float4 wv =
                        *(const float4*)&wsm[ii][dr * TC + dc][nx * 4];
                    #pragma unroll
                    for (int j = 0; j < 4; j++) {
                        acc[j][0] += xr[j + dc] * wv.x;
                        acc[j][1] += xr[j + dc] * wv.y;
                        acc[j][2] += xr[j + dc] * wv.z;
                        acc[j][3] += xr[j + dc] * wv.w;
                    }
                }
            }
        }
        __syncthreads();
    }

    int pp = p0 + tr_;
    if (pp < PH) {
        int yrow = 2 * pp + PRY;
        #pragma unroll
        for (int j = 0; j < 4; j++) {
            int qq = q0 + qj0 + j;
            if (qq < PW) {
                int ycol = 2 * qq + PCY;
                #pragma unroll
                for (int n = 0; n < 4; n++) {
                    int og = o0 + nx * 4 + n;
                    g_y[((b * COUT + og) * HY + yrow) * HY + ycol] = acc[j][n];
                }
            }
        }
    }
}

// ---------------- k6: blur(4x4 FIR, pad 1) * demod + bias -> LReLU * sqrt(2) -
__global__ void k_blur(const float* __restrict__ bias, float* __restrict__ out) {
    int o = blockIdx.x;
    int b = blockIdx.y;
    __shared__ float ys[67][68];
    const float* yp = g_y + (b * COUT + o) * (HY * HY);
    for (int idx = threadIdx.x; idx < 67 * 67; idx += 256) {
        int r = idx / 67, cc = idx - r * 67;
        int yr = r - 1, yc = cc - 1;
        float v = 0.f;
        if (yr >= 0 && yr < HY && yc >= 0 && yc < HY) v = yp[yr * HY + yc];
        ys[r][cc] = v;
    }
    __syncthreads();
    float dm = g_demod[b * COUT + o];
    float bs = bias[o];
    const float av0 = 0.25f, av1 = 0.75f;  // [1,3,3,1]/4; bk = outer/16
    float av[4] = {av0, av1, av1, av0};
    for (int idx = threadIdx.x; idx < HO * HO; idx += 256) {
        int p = idx >> 6, q = idx & 63;
        float acc = 0.f;
        #pragma unroll
        for (int u = 0; u < 4; u++) {
            float ru = 0.f;
            #pragma unroll
            for (int v = 0; v < 4; v++) ru += av[v] * ys[p + u][q + v];
            acc += av[u] * ru;
        }
        float z = dm * acc + bs;
        z = (z >= 0.f) ? z : 0.2f * z;
        out[((b * COUT + o) * HO + p) * HO + q] = z * 1.4142135623730951f;
    }
}

// ---------------- launch --------------------------------------------------
extern "C" void kernel_launch(void* const* d_in, const int* in_sizes, int n_in,
                              void* d_out, int out_size) {
    const float* x      = (const float*)d_in[0];
    const float* style  = (const float*)d_in[1];
    const float* weight = (const float*)d_in[2];
    const float* mod_w  = (const float*)d_in[3];
    const float* mod_b  = (const float*)d_in[4];
    const float* bias   = (const float*)d_in[5];
    float* out = (float*)d_out;

    k_style<<<512, 256>>>(style, mod_w, mod_b);
    k_demod<<<512, 256>>>(weight);
    k_xs<<<(NB * CIN * HH * HH + 255) / 256, 256>>>(x);
    k_wc<<<(COUT * CIN + 255) / 256, 256>>>(weight);

    dim3 g22(5 * 5, COUT / 64, NB);
    k_conv<2, 2><<<g22, 256>>>();
    dim3 g21(5 * 4, COUT / 64, NB);
    k_conv<2, 1><<<g21, 256>>>();
    dim3 g12(4 * 5, COUT / 64, NB);
    k_conv<1, 2><<<g12, 256>>>();
    dim3 g11(4 * 4, COUT / 64, NB);
    k_conv<1, 1><<<g11, 256>>>();

    dim3 gb(COUT, NB);
    k_blur<<<gb, 256>>>(bias, out);
}

// round 5
// speedup vs baseline: 3.9603x; 3.9603x over previous
#include <cuda_runtime.h>
#include <cstdint>
#include <math.h>

#define NB 8
#define CC 512
#define HO 64
#define XPW 34            // padded x width (32 + 1 each side)
#define XPP (XPW*XPW)     // 1156 floats per (b,i) plane

// cls0 even/even P=33 Q=33 TAPS=4 ; cls1 even/odd P=33 Q=32 TAPS=2
// cls2 odd/even  P=32 Q=33 TAPS=2 ; cls3 odd/odd  P=32 Q=32 TAPS=1
#define PQ0 1089
#define PQ1 1056
#define PQ2 1056
#define PQ3 1024

#define WB0 0
#define WB1 (WB0 + CC*2048)
#define WB2 (WB1 + CC*1024)
#define WB3 (WB2 + CC*1024)
#define W_TOT (WB3 + CC*512)

#define YB0 0
#define YB1 (YB0 + NB*CC*PQ0)
#define YB2 (YB1 + NB*CC*PQ1)
#define YB3 (YB2 + NB*CC*PQ2)
#define Y_TOT (YB3 + NB*CC*PQ3)

__device__ float g_s[NB * CC];
__device__ float g_demod[NB * CC];
__device__ float g_xp[NB * CC * XPP];
__device__ float g_W[W_TOT];
__device__ float g_y[Y_TOT];

// ---------------- mma / tf32 helpers ----------------
__device__ __forceinline__ uint32_t to_tf32(float f) {
    uint32_t u;
    asm("cvt.rna.tf32.f32 %0, %1;" : "=r"(u) : "f"(f));
    return u;
}
__device__ __forceinline__ void mma8(float* c, const uint32_t* a, const uint32_t* b) {
    asm volatile(
        "mma.sync.aligned.m16n8k8.row.col.f32.tf32.tf32.f32 "
        "{%0,%1,%2,%3}, {%4,%5,%6,%7}, {%8,%9}, {%0,%1,%2,%3};"
        : "+f"(c[0]), "+f"(c[1]), "+f"(c[2]), "+f"(c[3])
        : "r"(a[0]), "r"(a[1]), "r"(a[2]), "r"(a[3]), "r"(b[0]), "r"(b[1]));
}

// ---------------- k1: style modulation ----------------
__global__ void k_style(const float* __restrict__ style,
                        const float* __restrict__ mod_w,
                        const float* __restrict__ mod_b) {
    int warp = (blockIdx.x * blockDim.x + threadIdx.x) >> 5;
    int lane = threadIdx.x & 31;
    if (warp >= NB * CC) return;
    int b = warp >> 9, i = warp & 511;
    const float* st = style + b * 512;
    const float* mw = mod_w + i * 512;
    float acc = 0.f;
    for (int d = lane; d < 512; d += 32) acc += st[d] * mw[d];
    #pragma unroll
    for (int off = 16; off; off >>= 1) acc += __shfl_down_sync(0xffffffffu, acc, off);
    if (lane == 0) g_s[warp] = acc * 0.04419417382415922f + mod_b[i];
}

// ---------------- k2: demod ----------------
__global__ void k_demod(const float* __restrict__ weight) {
    int warp = (blockIdx.x * blockDim.x + threadIdx.x) >> 5;
    int lane = threadIdx.x & 31;
    if (warp >= NB * CC) return;
    int b = warp >> 9, o = warp & 511;
    float acc = 0.f;
    for (int i = lane; i < CC; i += 32) {
        const float* wp = weight + (o * CC + i) * 9;
        float ws = 0.f;
        #pragma unroll
        for (int k = 0; k < 9; k++) ws += wp[k] * wp[k];
        float sv = g_s[b * CC + i];
        acc += ws * sv * sv;
    }
    #pragma unroll
    for (int off = 16; off; off >>= 1) acc += __shfl_down_sync(0xffffffffu, acc, off);
    if (lane == 0) g_demod[warp] = rsqrtf(acc * (1.0f / 4608.0f) + 1e-8f);
}

// ---------------- k3: per-class weights, K-major (k = i*TAPS + tap) ---------
__global__ void k_wc(const float* __restrict__ weight) {
    int idx = blockIdx.x * blockDim.x + threadIdx.x;
    if (idx >= CC * CC) return;
    int o = idx >> 9, i = idx & 511;
    const float* wp = weight + (size_t)idx * 9;
    float w00 = wp[0], w01 = wp[1], w02 = wp[2];
    float w10 = wp[3], w11 = wp[4], w12 = wp[5];
    float w20 = wp[6], w21 = wp[7], w22 = wp[8];
    *(float4*)(g_W + WB0 + o * 2048 + i * 4) = make_float4(w22, w20, w02, w00);
    *(float2*)(g_W + WB1 + o * 1024 + i * 2) = make_float2(w21, w01);
    *(float2*)(g_W + WB2 + o * 1024 + i * 2) = make_float2(w12, w10);
    g_W[WB3 + o * 512 + i] = w11;
}

// ---------------- k4: padded + style-prescaled input ----------------
__global__ void k_xpad(const float* __restrict__ x) {
    int idx = blockIdx.x * blockDim.x + threadIdx.x;
    if (idx >= NB * CC * XPP) return;
    int bi = idx / XPP;
    int rem = idx - bi * XPP;
    int r = rem / XPW, c = rem - r * XPW;
    float v = 0.f;
    if (r >= 1 && r <= 32 && c >= 1 && c <= 32)
        v = x[((size_t)bi << 10) + (r - 1) * 32 + (c - 1)] * g_s[bi]
            * 0.014731391274719739f;  // 1/sqrt(512*9)
    g_xp[idx] = v;
}

// ---------------- A-tap gather: 4 consecutive k for one output pixel --------
__device__ __forceinline__ float4 gatherA(int cls, int rb, int k0) {
    float4 v;
    if (cls == 0) {
        const float* p = g_xp + rb + (k0 >> 2) * XPP;
        v.x = p[0]; v.y = p[1]; v.z = p[XPW]; v.w = p[XPW + 1];
    } else if (cls == 1) {
        const float* p = g_xp + rb + (k0 >> 1) * XPP + 1;
        v.x = p[0]; v.y = p[XPW]; v.z = p[XPP]; v.w = p[XPP + XPW];
    } else if (cls == 2) {
        const float* p = g_xp + rb + (k0 >> 1) * XPP + XPW;
        v.x = p[0]; v.y = p[1]; v.z = p[XPP]; v.w = p[XPP + 1];
    } else {
        const float* p = g_xp + rb + k0 * XPP + XPW + 1;
        v.x = p[0]; v.y = p[XPP]; v.z = p[2 * XPP]; v.w = p[3 * XPP];
    }
    return v;
}

// ---------------- k5: merged tf32 mma.sync GEMM ----------------
// CTA 128(M) x 128(N), K-chunk 16, 8 warps of 32x64, double-buffered smem.
// Static smem (uint words): A bufs [2][128][20] @0, B bufs [2][128][20] @5120.
#define KSTRIDE 20
#define BUFU 2560            // 128*20 words per buffer

__global__ void __launch_bounds__(256) k_gemm() {
    __shared__ uint32_t smem_u[4 * BUFU];   // 40960 bytes, static (no attr needed)
    int cls = blockIdx.z;
    int PQ, Q, KC, wb;
    long long yb;
    if (cls == 0)      { PQ = PQ0; Q = 33; KC = 2048; wb = WB0; yb = YB0; }
    else if (cls == 1) { PQ = PQ1; Q = 32; KC = 1024; wb = WB1; yb = YB1; }
    else if (cls == 2) { PQ = PQ2; Q = 33; KC = 1024; wb = WB2; yb = YB2; }
    else               { PQ = PQ3; Q = 32; KC = 512;  wb = WB3; yb = YB3; }
    int MC = NB * PQ;
    int mtiles = (MC + 127) >> 7;
    if ((int)blockIdx.x >= mtiles) return;

    int tid = threadIdx.x, wid = tid >> 5, lane = tid & 31;
    int gid = lane >> 2, tig = lane & 3;
    int wM = wid & 3, wN = wid >> 2;
    int m0 = blockIdx.x * 128, o0 = blockIdx.y * 128;

    // staging assignment: rows r0, r0+64 ; k-group kg (4 floats)
    int r0 = tid >> 2, kg = tid & 3;
    int arb0 = 0, arb1 = 0;
    bool av0 = (m0 + r0) < MC, av1 = (m0 + r0 + 64) < MC;
    {
        int m = m0 + r0;
        if (av0) {
            int b = m / PQ, r = m - b * PQ, p = r / Q, q = r - p * Q;
            arb0 = (b * CC) * XPP + p * XPW + q;
        }
        m = m0 + r0 + 64;
        if (av1) {
            int b = m / PQ, r = m - b * PQ, p = r / Q, q = r - p * Q;
            arb1 = (b * CC) * XPP + p * XPW + q;
        }
    }
    const float* Wb = g_W + wb;

    float acc[2][8][4];
    #pragma unroll
    for (int mi = 0; mi < 2; mi++)
        #pragma unroll
        for (int ni = 0; ni < 8; ni++)
            #pragma unroll
            for (int j = 0; j < 4; j++) acc[mi][ni][j] = 0.f;

    const float4 fz = make_float4(0.f, 0.f, 0.f, 0.f);
    float4 a0, a1, b0, b1;

    // fetch chunk 0
    {
        int k0 = kg * 4;
        a0 = av0 ? gatherA(cls, arb0, k0) : fz;
        a1 = av1 ? gatherA(cls, arb1, k0) : fz;
        b0 = *(const float4*)(Wb + (size_t)(o0 + r0) * KC + k0);
        b1 = *(const float4*)(Wb + (size_t)(o0 + r0 + 64) * KC + k0);
    }
    // stage chunk 0 -> buf 0
    {
        uint32_t* Ad = smem_u;
        uint32_t* Bd = smem_u + 2 * BUFU;
        uint32_t* p = Ad + r0 * KSTRIDE + kg * 4;
        p[0] = to_tf32(a0.x); p[1] = to_tf32(a0.y); p[2] = to_tf32(a0.z); p[3] = to_tf32(a0.w);
        p = Ad + (r0 + 64) * KSTRIDE + kg * 4;
        p[0] = to_tf32(a1.x); p[1] = to_tf32(a1.y); p[2] = to_tf32(a1.z); p[3] = to_tf32(a1.w);
        p = Bd + r0 * KSTRIDE + kg * 4;
        p[0] = to_tf32(b0.x); p[1] = to_tf32(b0.y); p[2] = to_tf32(b0.z); p[3] = to_tf32(b0.w);
        p = Bd + (r0 + 64) * KSTRIDE + kg * 4;
        p[0] = to_tf32(b1.x); p[1] = to_tf32(b1.y); p[2] = to_tf32(b1.z); p[3] = to_tf32(b1.w);
    }
    __syncthreads();

    int nk = KC >> 4;
    for (int ic = 0; ic < nk; ic++) {
        bool nxt = (ic + 1 < nk);
        if (nxt) {
            int k0 = (ic + 1) * 16 + kg * 4;
            a0 = av0 ? gatherA(cls, arb0, k0) : fz;
            a1 = av1 ? gatherA(cls, arb1, k0) : fz;
            b0 = *(const float4*)(Wb + (size_t)(o0 + r0) * KC + k0);
            b1 = *(const float4*)(Wb + (size_t)(o0 + r0 + 64) * KC + k0);
        }
        // compute current buffer
        {
            const uint32_t* As = smem_u + (ic & 1) * BUFU;
            const uint32_t* Bs = smem_u + 2 * BUFU + (ic & 1) * BUFU;
            #pragma unroll
            for (int ks = 0; ks < 16; ks += 8) {
                uint32_t af[2][4];
                #pragma unroll
                for (int mi = 0; mi < 2; mi++) {
                    int rb = wM * 32 + mi * 16 + gid;
                    af[mi][0] = As[rb * KSTRIDE + ks + tig];
                    af[mi][1] = As[(rb + 8) * KSTRIDE + ks + tig];
                    af[mi][2] = As[rb * KSTRIDE + ks + tig + 4];
                    af[mi][3] = As[(rb + 8) * KSTRIDE + ks + tig + 4];
                }
                uint32_t bf[8][2];
                #pragma unroll
                for (int ni = 0; ni < 8; ni++) {
                    int nb = wN * 64 + ni * 8 + gid;
                    bf[ni][0] = Bs[nb * KSTRIDE + ks + tig];
                    bf[ni][1] = Bs[nb * KSTRIDE + ks + tig + 4];
                }
                #pragma unroll
                for (int mi = 0; mi < 2; mi++)
                    #pragma unroll
                    for (int ni = 0; ni < 8; ni++)
                        mma8(acc[mi][ni], af[mi], bf[ni]);
            }
        }
        if (nxt) {
            uint32_t* Ad = smem_u + ((ic + 1) & 1) * BUFU;
            uint32_t* Bd = smem_u + 2 * BUFU + ((ic + 1) & 1) * BUFU;
            uint32_t* p = Ad + r0 * KSTRIDE + kg * 4;
            p[0] = to_tf32(a0.x); p[1] = to_tf32(a0.y); p[2] = to_tf32(a0.z); p[3] = to_tf32(a0.w);
            p = Ad + (r0 + 64) * KSTRIDE + kg * 4;
            p[0] = to_tf32(a1.x); p[1] = to_tf32(a1.y); p[2] = to_tf32(a1.z); p[3] = to_tf32(a1.w);
            p = Bd + r0 * KSTRIDE + kg * 4;
            p[0] = to_tf32(b0.x); p[1] = to_tf32(b0.y); p[2] = to_tf32(b0.z); p[3] = to_tf32(b0.w);
            p = Bd + (r0 + 64) * KSTRIDE + kg * 4;
            p[0] = to_tf32(b1.x); p[1] = to_tf32(b1.y); p[2] = to_tf32(b1.z); p[3] = to_tf32(b1.w);
            __syncthreads();
        }
    }
    __syncthreads();

    // ---- epilogue: transpose through smem, coalesced stores along pq -------
    float* eps = (float*)smem_u;  // [64][132] floats = 33792 B <= 40960 B
    #pragma unroll
    for (int h = 0; h < 2; h++) {
        if (wN == h) {
            #pragma unroll
            for (int mi = 0; mi < 2; mi++) {
                #pragma unroll
                for (int ni = 0; ni < 8; ni++) {
                    int ml = wM * 32 + mi * 16 + gid;
                    int nl = ni * 8 + tig * 2;
                    eps[nl * 132 + ml]           = acc[mi][ni][0];
                    eps[(nl + 1) * 132 + ml]     = acc[mi][ni][1];
                    eps[nl * 132 + ml + 8]       = acc[mi][ni][2];
                    eps[(nl + 1) * 132 + ml + 8] = acc[mi][ni][3];
                }
            }
        }
        __syncthreads();
        #pragma unroll
        for (int s = 0; s < 8; s++) {
            int nl = wid * 8 + s;
            int o = o0 + h * 64 + nl;
            float4 v = *(const float4*)(eps + nl * 132 + lane * 4);
            float vv[4] = {v.x, v.y, v.z, v.w};
            #pragma unroll
            for (int j = 0; j < 4; j++) {
                int m = m0 + lane * 4 + j;
                if (m < MC) {
                    int b = m / PQ;
                    int pq = m - b * PQ;
                    g_y[yb + (size_t)(b * CC + o) * PQ + pq] = vv[j];
                }
            }
        }
        __syncthreads();
    }
}

// ---------------- k6: blur + demod + bias + lrelu ----------------
__global__ void k_blur(const float* __restrict__ bias, float* __restrict__ out) {
    int o = blockIdx.x;
    int b = blockIdx.y;
    __shared__ float ys[67][68];
    int bo = b * CC + o;
    const float* pl0 = g_y + YB0 + (size_t)bo * PQ0;
    const float* pl1 = g_y + YB1 + (size_t)bo * PQ1;
    const float* pl2 = g_y + YB2 + (size_t)bo * PQ2;
    const float* pl3 = g_y + YB3 + (size_t)bo * PQ3;
    for (int idx = threadIdx.x; idx < 67 * 67; idx += 256) {
        int r0 = idx / 67, c0 = idx - r0 * 67;
        int yr = r0 - 1, yc = c0 - 1;
        float v = 0.f;
        if (yr >= 0 && yr < 65 && yc >= 0 && yc < 65) {
            int p = yr >> 1, q = yc >> 1;
            if (yr & 1) v = (yc & 1) ? pl3[p * 32 + q] : pl2[p * 33 + q];
            else        v = (yc & 1) ? pl1[p * 32 + q] : pl0[p * 33 + q];
        }
        ys[r0][c0] = v;
    }
    __syncthreads();
    float dm = g_demod[bo];
    float bs = bias[o];
    float av[4] = {0.25f, 0.75f, 0.75f, 0.25f};
    for (int idx = threadIdx.x; idx < HO * HO; idx += 256) {
        int p = idx >> 6, q = idx & 63;
        float acc = 0.f;
        #pragma unroll
        for (int u = 0; u < 4; u++) {
            float ru = 0.f;
            #pragma unroll
            for (int v = 0; v < 4; v++) ru += av[v] * ys[p + u][q + v];
            acc += av[u] * ru;
        }
        float z = dm * acc + bs;
        z = (z >= 0.f) ? z : 0.2f * z;
        out[((size_t)bo * HO + p) * HO + q] = z * 1.4142135623730951f;
    }
}

// ---------------- launch ----------------
extern "C" void kernel_launch(void* const* d_in, const int* in_sizes, int n_in,
                              void* d_out, int out_size) {
    const float* x      = (const float*)d_in[0];
    const float* style  = (const float*)d_in[1];
    const float* weight = (const float*)d_in[2];
    const float* mod_w  = (const float*)d_in[3];
    const float* mod_b  = (const float*)d_in[4];
    const float* bias   = (const float*)d_in[5];
    float* out = (float*)d_out;

    k_style<<<512, 256>>>(style, mod_w, mod_b);
    k_demod<<<512, 256>>>(weight);
    k_wc<<<(CC * CC) / 256, 256>>>(weight);
    k_xpad<<<(NB * CC * XPP + 255) / 256, 256>>>(x);

    k_gemm<<<dim3(69, 4, 4), 256>>>();

    k_blur<<<dim3(CC, NB), 256>>>(bias, out);
}

// round 9
// speedup vs baseline: 4.2283x; 1.0677x over previous
#include <cuda_runtime.h>
#include <cstdint>
#include <math.h>

#define NB 8
#define CC 512
#define HO 64
#define XPW 34            // padded x width (32 + 1 each side)
#define XPP (XPW*XPW)     // 1156 floats per (b,i) plane

// cls0 even/even P=33 Q=33 TAPS=4 ; cls1 even/odd P=33 Q=32 TAPS=2
// cls2 odd/even  P=32 Q=33 TAPS=2 ; cls3 odd/odd  P=32 Q=32 TAPS=1
#define PQ0 1089
#define PQ1 1056
#define PQ2 1056
#define PQ3 1024

#define WB0 0
#define WB1 (WB0 + CC*2048)
#define WB2 (WB1 + CC*1024)
#define WB3 (WB2 + CC*1024)
#define W_TOT (WB3 + CC*512)

#define YB0 0
#define YB1 (YB0 + NB*CC*PQ0)
#define YB2 (YB1 + NB*CC*PQ1)
#define YB3 (YB2 + NB*CC*PQ2)
#define Y_TOT (YB3 + NB*CC*PQ3)

__device__ float g_s[NB * CC];
__device__ float g_demod[NB * CC];
__device__ float g_wsum[CC * CC];        // sum_k w^2 per (o,i)
__device__ float g_xp[NB * CC * XPP];    // padded, prescaled, tf32-rounded
__device__ float g_W[W_TOT];             // per-class weights, tf32-rounded
__device__ float g_y[Y_TOT];

// ---------------- helpers ----------------
__device__ __forceinline__ uint32_t to_tf32(float f) {
    uint32_t u;
    asm("cvt.rna.tf32.f32 %0, %1;" : "=r"(u) : "f"(f));
    return u;
}
__device__ __forceinline__ float to_tf32f(float f) {
    return __uint_as_float(to_tf32(f));
}
__device__ __forceinline__ void mma8(float* c, const uint32_t* a, const uint32_t* b) {
    asm volatile(
        "mma.sync.aligned.m16n8k8.row.col.f32.tf32.tf32.f32 "
        "{%0,%1,%2,%3}, {%4,%5,%6,%7}, {%8,%9}, {%0,%1,%2,%3};"
        : "+f"(c[0]), "+f"(c[1]), "+f"(c[2]), "+f"(c[3])
        : "r"(a[0]), "r"(a[1]), "r"(a[2]), "r"(a[3]), "r"(b[0]), "r"(b[1]));
}

// ---------------- k1: style modulation ----------------
__global__ void k_style(const float* __restrict__ style,
                        const float* __restrict__ mod_w,
                        const float* __restrict__ mod_b) {
    int warp = (blockIdx.x * blockDim.x + threadIdx.x) >> 5;
    int lane = threadIdx.x & 31;
    if (warp >= NB * CC) return;
    int b = warp >> 9, i = warp & 511;
    const float* st = style + b * 512;
    const float* mw = mod_w + i * 512;
    float acc = 0.f;
    for (int d = lane; d < 512; d += 32) acc += st[d] * mw[d];
    #pragma unroll
    for (int off = 16; off; off >>= 1) acc += __shfl_down_sync(0xffffffffu, acc, off);
    if (lane == 0) g_s[warp] = acc * 0.04419417382415922f + mod_b[i];
}

// ---------------- k3: per-class weights (tf32-rounded) + wsum ----------------
__global__ void k_wc(const float* __restrict__ weight) {
    int idx = blockIdx.x * blockDim.x + threadIdx.x;
    if (idx >= CC * CC) return;
    int o = idx >> 9, i = idx & 511;
    const float* wp = weight + (size_t)idx * 9;
    float w00 = wp[0], w01 = wp[1], w02 = wp[2];
    float w10 = wp[3], w11 = wp[4], w12 = wp[5];
    float w20 = wp[6], w21 = wp[7], w22 = wp[8];
    g_wsum[idx] = w00*w00 + w01*w01 + w02*w02 + w10*w10 + w11*w11
                + w12*w12 + w20*w20 + w21*w21 + w22*w22;
    *(float4*)(g_W + WB0 + o * 2048 + i * 4) =
        make_float4(to_tf32f(w22), to_tf32f(w20), to_tf32f(w02), to_tf32f(w00));
    *(float2*)(g_W + WB1 + o * 1024 + i * 2) = make_float2(to_tf32f(w21), to_tf32f(w01));
    *(float2*)(g_W + WB2 + o * 1024 + i * 2) = make_float2(to_tf32f(w12), to_tf32f(w10));
    g_W[WB3 + o * 512 + i] = to_tf32f(w11);
}

// ---------------- k2: demod from wsum (8 MB instead of 150 MB) --------------
__global__ void k_demod() {
    int warp = (blockIdx.x * blockDim.x + threadIdx.x) >> 5;
    int lane = threadIdx.x & 31;
    if (warp >= NB * CC) return;
    int b = warp >> 9, o = warp & 511;
    const float* ws = g_wsum + o * CC;
    const float* sv = g_s + b * CC;
    float acc = 0.f;
    for (int i = lane; i < CC; i += 32) {
        float s = sv[i];
        acc += ws[i] * s * s;
    }
    #pragma unroll
    for (int off = 16; off; off >>= 1) acc += __shfl_down_sync(0xffffffffu, acc, off);
    if (lane == 0) g_demod[warp] = rsqrtf(acc * (1.0f / 4608.0f) + 1e-8f);
}

// ---------------- k4: padded + prescaled + tf32-rounded input ---------------
__global__ void k_xpad(const float* __restrict__ x) {
    int idx = blockIdx.x * blockDim.x + threadIdx.x;
    if (idx >= NB * CC * XPP) return;
    int bi = idx / XPP;
    int rem = idx - bi * XPP;
    int r = rem / XPW, c = rem - r * XPW;
    float v = 0.f;
    if (r >= 1 && r <= 32 && c >= 1 && c <= 32)
        v = to_tf32f(x[((size_t)bi << 10) + (r - 1) * 32 + (c - 1)] * g_s[bi]
                     * 0.014731391274719739f);  // 1/sqrt(512*9)
    g_xp[idx] = v;
}

// ---------------- A-tap gather: 4 consecutive k for one output pixel --------
__device__ __forceinline__ float4 gatherA(int cls, int rb, int k0) {
    float4 v;
    if (cls == 0) {
        const float* p = g_xp + rb + (k0 >> 2) * XPP;
        v.x = p[0]; v.y = p[1]; v.z = p[XPW]; v.w = p[XPW + 1];
    } else if (cls == 1) {
        const float* p = g_xp + rb + (k0 >> 1) * XPP + 1;
        v.x = p[0]; v.y = p[XPW]; v.z = p[XPP]; v.w = p[XPP + XPW];
    } else if (cls == 2) {
        const float* p = g_xp + rb + (k0 >> 1) * XPP + XPW;
        v.x = p[0]; v.y = p[1]; v.z = p[XPP]; v.w = p[XPP + 1];
    } else {
        const float* p = g_xp + rb + k0 * XPP + XPW + 1;
        v.x = p[0]; v.y = p[XPP]; v.z = p[2 * XPP]; v.w = p[3 * XPP];
    }
    return v;
}

// ---------------- k5: merged tf32 mma.sync GEMM (R5 skeleton, raw-bit stage) -
// CTA 128(M) x 128(N), K-chunk 16, 8 warps of 32x64, double-buffered smem.
#define KSTRIDE 20
#define BUFU 2560            // 128*20 words per buffer

__global__ void __launch_bounds__(256) k_gemm() {
    __shared__ uint32_t smem_u[4 * BUFU];   // 40960 bytes, static
    int cls = blockIdx.z;
    int PQ, Q, KC, wb;
    long long yb;
    if (cls == 0)      { PQ = PQ0; Q = 33; KC = 2048; wb = WB0; yb = YB0; }
    else if (cls == 1) { PQ = PQ1; Q = 32; KC = 1024; wb = WB1; yb = YB1; }
    else if (cls == 2) { PQ = PQ2; Q = 33; KC = 1024; wb = WB2; yb = YB2; }
    else               { PQ = PQ3; Q = 32; KC = 512;  wb = WB3; yb = YB3; }
    int MC = NB * PQ;
    int mtiles = (MC + 127) >> 7;
    if ((int)blockIdx.x >= mtiles) return;

    int tid = threadIdx.x, wid = tid >> 5, lane = tid & 31;
    int gid = lane >> 2, tig = lane & 3;
    int wM = wid & 3, wN = wid >> 2;
    int m0 = blockIdx.x * 128, o0 = blockIdx.y * 128;

    // staging assignment: rows r0, r0+64 ; k-group kg (4 floats)
    int r0 = tid >> 2, kg = tid & 3;
    int arb0 = 0, arb1 = 0;
    bool av0 = (m0 + r0) < MC, av1 = (m0 + r0 + 64) < MC;
    {
        int m = m0 + r0;
        if (av0) {
            int b = m / PQ, r = m - b * PQ, p = r / Q, q = r - p * Q;
            arb0 = (b * CC) * XPP + p * XPW + q;
        }
        m = m0 + r0 + 64;
        if (av1) {
            int b = m / PQ, r = m - b * PQ, p = r / Q, q = r - p * Q;
            arb1 = (b * CC) * XPP + p * XPW + q;
        }
    }
    const float* Wb = g_W + wb;

    float acc[2][8][4];
    #pragma unroll
    for (int mi = 0; mi < 2; mi++)
        #pragma unroll
        for (int ni = 0; ni < 8; ni++)
            #pragma unroll
            for (int j = 0; j < 4; j++) acc[mi][ni][j] = 0.f;

    const float4 fz = make_float4(0.f, 0.f, 0.f, 0.f);
    float4 a0, a1, b0, b1;

    // fetch chunk 0 (data already tf32-rounded in memory)
    {
        int k0 = kg * 4;
        a0 = av0 ? gatherA(cls, arb0, k0) : fz;
        a1 = av1 ? gatherA(cls, arb1, k0) : fz;
        b0 = *(const float4*)(Wb + (size_t)(o0 + r0) * KC + k0);
        b1 = *(const float4*)(Wb + (size_t)(o0 + r0 + 64) * KC + k0);
    }
    // stage chunk 0 -> buf 0 (raw bit copy, no cvt)
    {
        float* Ad = (float*)smem_u;
        float* Bd = (float*)(smem_u + 2 * BUFU);
        *(float4*)(Ad + r0 * KSTRIDE + kg * 4) = a0;
        *(float4*)(Ad + (r0 + 64) * KSTRIDE + kg * 4) = a1;
        *(float4*)(Bd + r0 * KSTRIDE + kg * 4) = b0;
        *(float4*)(Bd + (r0 + 64) * KSTRIDE + kg * 4) = b1;
    }
    __syncthreads();

    int nk = KC >> 4;
    for (int ic = 0; ic < nk; ic++) {
        bool nxt = (ic + 1 < nk);
        if (nxt) {
            int k0 = (ic + 1) * 16 + kg * 4;
            a0 = av0 ? gatherA(cls, arb0, k0) : fz;
            a1 = av1 ? gatherA(cls, arb1, k0) : fz;
            b0 = *(const float4*)(Wb + (size_t)(o0 + r0) * KC + k0);
            b1 = *(const float4*)(Wb + (size_t)(o0 + r0 + 64) * KC + k0);
        }
        // compute current buffer
        {
            const uint32_t* As = smem_u + (ic & 1) * BUFU;
            const uint32_t* Bs = smem_u + 2 * BUFU + (ic & 1) * BUFU;
            #pragma unroll
            for (int ks = 0; ks < 16; ks += 8) {
                uint32_t af[2][4];
                #pragma unroll
                for (int mi = 0; mi < 2; mi++) {
                    int rb = wM * 32 + mi * 16 + gid;
                    af[mi][0] = As[rb * KSTRIDE + ks + tig];
                    af[mi][1] = As[(rb + 8) * KSTRIDE + ks + tig];
                    af[mi][2] = As[rb * KSTRIDE + ks + tig + 4];
                    af[mi][3] = As[(rb + 8) * KSTRIDE + ks + tig + 4];
                }
                uint32_t bf[8][2];
                #pragma unroll
                for (int ni = 0; ni < 8; ni++) {
                    int nb = wN * 64 + ni * 8 + gid;
                    bf[ni][0] = Bs[nb * KSTRIDE + ks + tig];
                    bf[ni][1] = Bs[nb * KSTRIDE + ks + tig + 4];
                }
                #pragma unroll
                for (int mi = 0; mi < 2; mi++)
                    #pragma unroll
                    for (int ni = 0; ni < 8; ni++)
                        mma8(acc[mi][ni], af[mi], bf[ni]);
            }
        }
        if (nxt) {
            float* Ad = (float*)(smem_u + ((ic + 1) & 1) * BUFU);
            float* Bd = (float*)(smem_u + 2 * BUFU + ((ic + 1) & 1) * BUFU);
            *(float4*)(Ad + r0 * KSTRIDE + kg * 4) = a0;
            *(float4*)(Ad + (r0 + 64) * KSTRIDE + kg * 4) = a1;
            *(float4*)(Bd + r0 * KSTRIDE + kg * 4) = b0;
            *(float4*)(Bd + (r0 + 64) * KSTRIDE + kg * 4) = b1;
            __syncthreads();
        }
    }
    __syncthreads();

    // ---- epilogue: transpose through smem, coalesced stores along pq -------
    float* eps = (float*)smem_u;  // [64][132] floats = 33792 B
    #pragma unroll
    for (int h = 0; h < 2; h++) {
        if (wN == h) {
            #pragma unroll
            for (int mi = 0; mi < 2; mi++) {
                #pragma unroll
                for (int ni = 0; ni < 8; ni++) {
                    int ml = wM * 32 + mi * 16 + gid;
                    int nl = ni * 8 + tig * 2;
                    eps[nl * 132 + ml]           = acc[mi][ni][0];
                    eps[(nl + 1) * 132 + ml]     = acc[mi][ni][1];
                    eps[nl * 132 + ml + 8]       = acc[mi][ni][2];
                    eps[(nl + 1) * 132 + ml + 8] = acc[mi][ni][3];
                }
            }
        }
        __syncthreads();
        #pragma unroll
        for (int s = 0; s < 8; s++) {
            int nl = wid * 8 + s;
            int o = o0 + h * 64 + nl;
            float4 v = *(const float4*)(eps + nl * 132 + lane * 4);
            float vv[4] = {v.x, v.y, v.z, v.w};
            #pragma unroll
            for (int j = 0; j < 4; j++) {
                int m = m0 + lane * 4 + j;
                if (m < MC) {
                    int b = m / PQ;
                    int pq = m - b * PQ;
                    g_y[yb + (size_t)(b * CC + o) * PQ + pq] = vv[j];
                }
            }
        }
        __syncthreads();
    }
}

// ---------------- k6: blur + demod + bias + lrelu ----------------
__global__ void k_blur(const float* __restrict__ bias, float* __restrict__ out) {
    int o = blockIdx.x;
    int b = blockIdx.y;
    __shared__ float ys[67][68];
    int bo = b * CC + o;
    const float* pl0 = g_y + YB0 + (size_t)bo * PQ0;
    const float* pl1 = g_y + YB1 + (size_t)bo * PQ1;
    const float* pl2 = g_y + YB2 + (size_t)bo * PQ2;
    const float* pl3 = g_y + YB3 + (size_t)bo * PQ3;
    int tid = threadIdx.x;
    // zero border lines (rows/cols 0 and 66)
    if (tid < 67) {
        ys[0][tid] = 0.f; ys[66][tid] = 0.f;
        ys[tid][0] = 0.f; ys[tid][66] = 0.f;
    }
    // dense, coalesced per-plane staging: ys[r0][c0] holds y[r0-1][c0-1]
    for (int idx = tid; idx < 1089; idx += 256) {        // pl0: yr=2p, yc=2q
        int p = idx / 33, q = idx - p * 33;
        ys[2 * p + 1][2 * q + 1] = pl0[idx];
    }
    for (int idx = tid; idx < 1056; idx += 256) {        // pl1: yr=2p, yc=2q+1
        int p = idx >> 5, q = idx & 31;
        ys[2 * p + 1][2 * q + 2] = pl1[idx];
    }
    for (int idx = tid; idx < 1056; idx += 256) {        // pl2: yr=2p+1, yc=2q
        int p = idx / 33, q = idx - p * 33;
        ys[2 * p + 2][2 * q + 1] = pl2[idx];
    }
    for (int idx = tid; idx < 1024; idx += 256) {        // pl3: yr=2p+1, yc=2q+1
        int p = idx >> 5, q = idx & 31;
        ys[2 * p + 2][2 * q + 2] = pl3[idx];
    }
    __syncthreads();
    float dm = g_demod[bo];
    float bs = bias[o];
    float av[4] = {0.25f, 0.75f, 0.75f, 0.25f};
    for (int idx = tid; idx < HO * HO; idx += 256) {
        int p = idx >> 6, q = idx & 63;
        float acc = 0.f;
        #pragma unroll
        for (int u = 0; u < 4; u++) {
            float ru = 0.f;
            #pragma unroll
            for (int v = 0; v < 4; v++) ru += av[v] * ys[p + u][q + v];
            acc += av[u] * ru;
        }
        float z = dm * acc + bs;
        z = (z >= 0.f) ? z : 0.2f * z;
        out[((size_t)bo * HO + p) * HO + q] = z * 1.4142135623730951f;
    }
}

// ---------------- launch ----------------
extern "C" void kernel_launch(void* const* d_in, const int* in_sizes, int n_in,
                              void* d_out, int out_size) {
    const float* x      = (const float*)d_in[0];
    const float* style  = (const float*)d_in[1];
    const float* weight = (const float*)d_in[2];
    const float* mod_w  = (const float*)d_in[3];
    const float* mod_b  = (const float*)d_in[4];
    const float* bias   = (const float*)d_in[5];
    float* out = (float*)d_out;

    k_style<<<512, 256>>>(style, mod_w, mod_b);
    k_wc<<<(CC * CC) / 256, 256>>>(weight);
    k_xpad<<<(NB * CC * XPP + 255) / 256, 256>>>(x);
    k_demod<<<512, 256>>>();

    k_gemm<<<dim3(69, 4, 4), 256>>>();

    k_blur<<<dim3(CC, NB), 256>>>(bias, out);
}